// round 14
// baseline (speedup 1.0000x reference)
#include <cuda_runtime.h>
#include <cuda_fp16.h>
#include <math.h>
#include <stdint.h>

#define T_TOK 2048
#define HIDDEN 5120
#define NH 32
#define DQ 128
#define DR 64
#define DV 128
#define QLORA 1536
#define KVLORA 512
#define KV_W (KVLORA + DR)        // 576
#define QDIM (DQ + DR)            // 192
#define KVUPW (NH * (DQ + DV))    // 8192
#define QW (NH * QDIM)            // 6144
#define ATTNW (NH * DV)           // 4096
#define CMBW (QLORA + KV_W)       // 2112

// ---------------- scratch (device globals; no runtime allocation) ----------
__device__ __half g_hid_h[T_TOK * HIDDEN];
__device__ __half g_wcmbT[CMBW * HIDDEN];    // [2112][5120] K-major
__device__ __half g_wqbT[QW * QLORA];        // [6144][1536]
__device__ __half g_wkvbT[KVUPW * KVLORA];   // [8192][512]
__device__ __half g_woT[HIDDEN * ATTNW];     // [5120][4096]
__device__ __half g_cmbh[T_TOK * CMBW];
__device__ __half g_qh[T_TOK * QW];
__device__ __half g_kvuph[T_TOK * KVUPW];
__device__ __half g_kpeh[T_TOK * DR];
__device__ __half g_attnh[T_TOK * ATTNW];

// ======================= helpers ===========================================
__device__ __forceinline__ uint32_t smem_u32(const void* p) {
    uint32_t a;
    asm("{ .reg .u64 t; cvta.to.shared.u64 t, %1; cvt.u32.u64 %0, t; }"
        : "=r"(a) : "l"(p));
    return a;
}

__device__ __forceinline__ float ex2f(float x) {
    float y;
    asm("ex2.approx.ftz.f32 %0, %1;" : "=f"(y) : "f"(x));
    return y;
}

__device__ __forceinline__ uint32_t ex2h2(uint32_t x) {
    uint32_t y;
    asm("ex2.approx.f16x2 %0, %1;" : "=r"(y) : "r"(x));
    return y;
}

__device__ __forceinline__ void mma_f16(float c[4], const uint32_t a[4],
                                        uint32_t b0, uint32_t b1) {
    asm volatile(
        "mma.sync.aligned.m16n8k16.row.col.f32.f16.f16.f32 "
        "{%0,%1,%2,%3}, {%4,%5,%6,%7}, {%8,%9}, {%0,%1,%2,%3};"
        : "+f"(c[0]), "+f"(c[1]), "+f"(c[2]), "+f"(c[3])
        : "r"(a[0]), "r"(a[1]), "r"(a[2]), "r"(a[3]), "r"(b0), "r"(b1));
}

__device__ __forceinline__ void ldsm4(uint32_t& r0, uint32_t& r1,
                                      uint32_t& r2, uint32_t& r3, uint32_t addr) {
    asm volatile("ldmatrix.sync.aligned.m8n8.x4.shared.b16 {%0,%1,%2,%3}, [%4];"
                 : "=r"(r0), "=r"(r1), "=r"(r2), "=r"(r3) : "r"(addr));
}

__device__ __forceinline__ void ldsm2(uint32_t& r0, uint32_t& r1, uint32_t addr) {
    asm volatile("ldmatrix.sync.aligned.m8n8.x2.shared.b16 {%0,%1}, [%2];"
                 : "=r"(r0), "=r"(r1) : "r"(addr));
}

__device__ __forceinline__ uint32_t h2u(__half2 h) {
    return *reinterpret_cast<uint32_t*>(&h);
}

// ---------------- fp32 -> fp16 conversion kernels --------------------------
__global__ void cvt_h_kernel(const float* __restrict__ in,
                             __half* __restrict__ o, int n4) {
    __half2* o2 = (__half2*)o;
    for (int i = blockIdx.x * 256 + threadIdx.x; i < n4; i += gridDim.x * 256) {
        float4 v = ((const float4*)in)[i];
        o2[2 * i] = __floats2half2_rn(v.x, v.y);
        o2[2 * i + 1] = __floats2half2_rn(v.z, v.w);
    }
}

// transpose + convert: in [Kd][Nd] fp32 -> out rows [orow + n][Kd] fp16
__global__ void cvtT_kernel(const float* __restrict__ in,
                            __half* __restrict__ out,
                            int Kd, int Nd, int orow) {
    __shared__ float t[32][33];
    const int n0 = blockIdx.x * 32, k0 = blockIdx.y * 32;
    const int x = threadIdx.x, y = threadIdx.y;  // (32,8)
#pragma unroll
    for (int j = 0; j < 4; j++)
        t[y + 8 * j][x] = in[(size_t)(k0 + y + 8 * j) * Nd + n0 + x];
    __syncthreads();
#pragma unroll
    for (int j = 0; j < 4; j++)
        out[(size_t)(orow + n0 + y + 8 * j) * Kd + k0 + x] =
            __float2half_rn(t[x][y + 8 * j]);
}

// ---------------- RoPE frequency -------------------------------------------
#define L2T_32 0.41524101186091903f   // log2(10000)/32
__device__ __forceinline__ float rope_freq(int i) {
    return exp2f(-(float)(i & 31) * L2T_32);
}

// ======================= fp16 mma.sync GEMM (64x64 warp tiles) =============
// C[M,N] = A[M,K] @ B[K,N]; A fp16 row-major [M][K]; B pre-transposed fp16
// [N][K]. M mult of 128, K mult of 32. CTA 128x128, BK=32, 3-stage cp.async,
// 128 thr = 4 warps (2x2 grid of 64x64 warp tiles), m16n8k16, ldmatrix.
#define RS 20
#define GSTG (128 * RS * 4)          // 10240 B per operand
#define GSTAGE (2 * GSTG)            // 20480 B per stage
#define GSMEM (3 * GSTAGE)           // 61440 B

__device__ __forceinline__ void g_load(uint32_t sbase, int s,
        const __half* __restrict__ A, int lda,
        const __half* __restrict__ BT, int ldb,
        int brow, int bcol, int N, int k0, int tid) {
    const uint32_t sA = sbase + s * GSTAGE;
    const uint32_t sB = sA + GSTG;
#pragma unroll
    for (int it = 0; it < 4; it++) {
        const int f = it * 128 + tid;
        const int r = f >> 2, c = f & 3;
        const uint32_t dst = sA + (r * RS + c * 4) * 4;
        const __half* src = A + (size_t)(brow + r) * lda + k0 + c * 8;
        asm volatile("cp.async.ca.shared.global [%0], [%1], 16;"
                     :: "r"(dst), "l"(src) : "memory");
    }
#pragma unroll
    for (int it = 0; it < 4; it++) {
        const int f = it * 128 + tid;
        const int r = f >> 2, c = f & 3;
        const uint32_t dst = sB + (r * RS + c * 4) * 4;
        const __half* src = BT + (size_t)(bcol + r) * ldb + k0 + c * 8;
        const int sz = (bcol + r < N) ? 16 : 0;
        asm volatile("cp.async.ca.shared.global [%0], [%1], 16, %2;"
                     :: "r"(dst), "l"(src), "r"(sz) : "memory");
    }
    asm volatile("cp.async.commit_group;" ::: "memory");
}

// mode: 0 plain; 1 q-RoPE ((col%192)>=128 rotated); 2 pe-split (col>=pe0 ->
// kpe). outfp32: C treated as float* (final output), else __half*.
__global__ __launch_bounds__(128, 2) void gemm_h(
        const __half* __restrict__ A, int lda,
        const __half* __restrict__ BT, int ldb,
        void* __restrict__ Cv, int ldc, int N, int K,
        float oscale, int mode, int pe0, int outfp32,
        const int* __restrict__ pos, __half* __restrict__ kpe) {
    extern __shared__ char sm[];
    const uint32_t sbase = smem_u32(sm);
    const int tid = threadIdx.x;
    const int lane = tid & 31;
    const int wid = tid >> 5;
    const int wm = wid >> 1, wn = wid & 1;   // 2x2 warp grid, 64x64 tiles
    const int brow = blockIdx.y * 128;
    const int bcol = blockIdx.x * 128;
    const int r = lane >> 2, c2 = lane & 3;

    float acc[4][8][4];
#pragma unroll
    for (int mi = 0; mi < 4; mi++)
#pragma unroll
        for (int ni = 0; ni < 8; ni++)
#pragma unroll
            for (int j = 0; j < 4; j++) acc[mi][ni][j] = 0.f;

    // ldmatrix per-lane byte offsets (base of the warp's 64-row block)
    const uint32_t aoff = ((wm * 64 + (lane & 7) + 8 * ((lane >> 3) & 1)) * RS
                           + 4 * (lane >> 4)) * 4;
    const uint32_t boff = ((wn * 64 + (lane & 7) + 8 * (lane >> 4)) * RS
                           + 4 * ((lane >> 3) & 1)) * 4;

    const int nch = K / 32;
    g_load(sbase, 0, A, lda, BT, ldb, brow, bcol, N, 0, tid);
    g_load(sbase, 1, A, lda, BT, ldb, brow, bcol, N, 32, tid);

    for (int i = 0; i < nch; i++) {
        const int s = i % 3;
        if (i + 1 < nch) {
            asm volatile("cp.async.wait_group 1;" ::: "memory");
        } else {
            asm volatile("cp.async.wait_group 0;" ::: "memory");
        }
        __syncthreads();

        const uint32_t sAb = sbase + s * GSTAGE;
        const uint32_t sBb = sAb + GSTG;

#pragma unroll
        for (int t = 0; t < 2; t++) {
            uint32_t a[4][4];
#pragma unroll
            for (int mi = 0; mi < 4; mi++)
                ldsm4(a[mi][0], a[mi][1], a[mi][2], a[mi][3],
                      sAb + aoff + mi * (16 * RS * 4) + t * 32);
#pragma unroll
            for (int nj = 0; nj < 4; nj++) {
                uint32_t b0, b1, b2, b3;
                ldsm4(b0, b1, b2, b3, sBb + boff + nj * (16 * RS * 4) + t * 32);
#pragma unroll
                for (int mi = 0; mi < 4; mi++) {
                    mma_f16(acc[mi][2 * nj], a[mi], b0, b1);
                    mma_f16(acc[mi][2 * nj + 1], a[mi], b2, b3);
                }
            }
        }
        if (i + 2 < nch)
            g_load(sbase, (i + 2) % 3, A, lda, BT, ldb, brow, bcol, N,
                   (i + 2) * 32, tid);
    }

    // ---- epilogue ----
    __half* Ch = (__half*)Cv;
    float* Cf = (float*)Cv;
#pragma unroll
    for (int mi = 0; mi < 4; mi++) {
        const int r0 = brow + wm * 64 + mi * 16 + r;
        const int r1 = r0 + 8;
        float fp0 = 0.f, fp1 = 0.f;
        if (mode != 0) { fp0 = (float)pos[r0]; fp1 = (float)pos[r1]; }
#pragma unroll
        for (int ni = 0; ni < 8; ni++) {
            const int col = bcol + wn * 64 + ni * 8 + c2 * 2;
            if (col >= N) continue;
            float x0 = acc[mi][ni][0] * oscale, x1 = acc[mi][ni][1] * oscale;
            float x2 = acc[mi][ni][2] * oscale, x3 = acc[mi][ni][3] * oscale;

            if (mode == 1) {
                const int d = col % QDIM;
                if (d >= DQ) {
                    const int i0 = d - DQ;
                    const float f0 = rope_freq(i0), f1 = rope_freq(i0 + 1);
                    float s0, c0, s1, c1;
                    sincosf(fp0 * f0, &s0, &c0);
                    sincosf(fp0 * f1, &s1, &c1);
                    float nx0 = x0 * c0 - x1 * s0;
                    float nx1 = x1 * c1 + x0 * s1;
                    x0 = nx0; x1 = nx1;
                    sincosf(fp1 * f0, &s0, &c0);
                    sincosf(fp1 * f1, &s1, &c1);
                    float nx2 = x2 * c0 - x3 * s0;
                    float nx3 = x3 * c1 + x2 * s1;
                    x2 = nx2; x3 = nx3;
                }
            } else if (mode == 2 && col >= pe0) {
                const int i0 = col - pe0;
                const float f0 = rope_freq(i0), f1 = rope_freq(i0 + 1);
                float s0, c0, s1, c1;
                sincosf(fp0 * f0, &s0, &c0);
                sincosf(fp0 * f1, &s1, &c1);
                ((__half2*)kpe)[((size_t)r0 * DR + i0) >> 1] =
                    __floats2half2_rn(x0 * c0 - x1 * s0, x1 * c1 + x0 * s1);
                sincosf(fp1 * f0, &s0, &c0);
                sincosf(fp1 * f1, &s1, &c1);
                ((__half2*)kpe)[((size_t)r1 * DR + i0) >> 1] =
                    __floats2half2_rn(x2 * c0 - x3 * s0, x3 * c1 + x2 * s1);
                continue;
            }

            if (outfp32) {
                *(float2*)&Cf[(size_t)r0 * ldc + col] = make_float2(x0, x1);
                *(float2*)&Cf[(size_t)r1 * ldc + col] = make_float2(x2, x3);
            } else {
                ((__half2*)Ch)[((size_t)r0 * ldc + col) >> 1] =
                    __floats2half2_rn(x0, x1);
                ((__half2*)Ch)[((size_t)r1 * ldc + col) >> 1] =
                    __floats2half2_rn(x2, x3);
            }
        }
    }
}

// ---------------- RMSNorm in place on fp16 ----------------------------------
__global__ void rmsnorm_h(__half* __restrict__ x, const float* __restrict__ g,
                          int width, int stride) {
    const int row = blockIdx.x;
    __half2* p = (__half2*)(x + (size_t)row * stride);
    const int tid = threadIdx.x;
    const int w2 = width >> 1;
    float s = 0.f;
    for (int i = tid; i < w2; i += 256) {
        float2 f = __half22float2(p[i]);
        s += f.x * f.x + f.y * f.y;
    }
    __shared__ float red[256];
    red[tid] = s;
    __syncthreads();
    for (int o = 128; o > 0; o >>= 1) {
        if (tid < o) red[tid] += red[tid + o];
        __syncthreads();
    }
    const float inv = rsqrtf(red[0] / (float)width + 1e-6f);
    for (int i = tid; i < w2; i += 256) {
        float2 f = __half22float2(p[i]);
        p[i] = __floats2half2_rn(f.x * inv * g[2 * i], f.y * inv * g[2 * i + 1]);
    }
}

// ================ flash attention, fp16 mma, log2-domain softmax ===========
// grid (16, 32): 128 q rows/CTA (ib REVERSED for causal load balance),
// 8 warps (16 rows each), k-tiles of 64. Q pre-scaled by scale*log2e.
// Ones-column in V computes row sums via PV mma. ldmatrix fragment loads.
#define QS 100   // sQ [128 q][96 u32 data]
#define KS 100   // sK [64 tok][96 u32]
#define VS 36    // sV [136 dv][32 u32]  (V transposed; rows 128..135 = ones/0)
#define PS 36    // sP [128 q][32 u32]
#define FLASH_SMEM ((128 * QS + 64 * KS + 136 * VS + 128 * PS) * 4)  // 114816

__global__ __launch_bounds__(256, 1) void flash_h(
        const __half* __restrict__ q, const __half* __restrict__ kvup,
        const __half* __restrict__ kpe, __half* __restrict__ out) {
    const int ib = gridDim.x - 1 - blockIdx.x;   // heavy CTAs first
    const int h = blockIdx.y;
    const int tid = threadIdx.x;
    const int lane = tid & 31;
    const int wid = tid >> 5;
    const int r = lane >> 2, c2 = lane & 3;

    extern __shared__ uint32_t fs[];
    uint32_t* sQ = fs;                 // 12800 u32
    uint32_t* sK = sQ + 128 * QS;      // 6400
    uint32_t* sV = sK + 64 * KS;       // 4896
    uint32_t* sP = sV + 136 * VS;      // 4608
    const uint32_t sQb = smem_u32(sQ);
    const uint32_t sKb = smem_u32(sK);
    const uint32_t sVb = smem_u32(sV);
    const uint32_t sPb = smem_u32(sP);

    // Q tile: 128 rows x 192 halves (96 u32)
    for (int idx = tid; idx < 128 * 24; idx += 256) {
        const int rr = idx / 24, d4 = idx % 24;
        *(float4*)&sQ[rr * QS + d4 * 4] =
            *(const float4*)(q + (size_t)(ib * 128 + rr) * QW + h * QDIM + d4 * 8);
    }
    // ones rows of V (dv=128 -> 1.0, 129..135 -> 0); written once
    for (int idx = tid; idx < 8 * 32; idx += 256) {
        const int rr = 128 + (idx >> 5), c = idx & 31;
        sV[rr * VS + c] = (rr == 128) ? 0x3C003C00u : 0u;
    }

    // ldmatrix per-lane byte offsets
    const uint32_t qoff = ((wid * 16 + (lane & 7) + 8 * ((lane >> 3) & 1)) * QS
                          + 4 * (lane >> 4)) * 4;
    const uint32_t koff = (((lane & 7) + 8 * (lane >> 4)) * KS
                          + 4 * ((lane >> 3) & 1)) * 4;
    const uint32_t poff = ((wid * 16 + (lane & 7) + 8 * ((lane >> 3) & 1)) * PS
                          + 4 * (lane >> 4)) * 4;
    const uint32_t voff = (((lane & 7) + 8 * (lane >> 4)) * VS
                          + 4 * ((lane >> 3) & 1)) * 4;
    const uint32_t ooff = ((128 + (lane & 7)) * VS + 4 * ((lane >> 3) & 1)) * 4;

    const int qr0 = ib * 128 + wid * 16 + r;
    float m0 = -INFINITY, m1 = -INFINITY;
    float O[16][4], Osum[4];
#pragma unroll
    for (int nt = 0; nt < 16; nt++)
#pragma unroll
        for (int j = 0; j < 4; j++) O[nt][j] = 0.f;
#pragma unroll
    for (int j = 0; j < 4; j++) Osum[j] = 0.f;

    const uint32_t* kvu = (const uint32_t*)kvup;
    const int njb = 2 * ib + 2;
    for (int jb = 0; jb < njb; jb++) {
        __syncthreads();
        // K tile: 64 tok x 192 halves (nope | roped pe)
        for (int idx = tid; idx < 64 * 24; idx += 256) {
            const int rr = idx / 24, d4 = idx % 24;
            const int kt = jb * 64 + rr;
            float4 v;
            if (d4 < 16)
                v = *(const float4*)(kvup + (size_t)kt * KVUPW + h * 256 + d4 * 8);
            else
                v = *(const float4*)(kpe + (size_t)kt * DR + (d4 - 16) * 8);
            *(float4*)&sK[rr * KS + d4 * 4] = v;
        }
        // V tile transposed: [dv 128][tok 64] via byte_perm repack
        for (int idx = tid; idx < 2048; idx += 256) {
            const int dvp = idx & 63, tkp = idx >> 6;
            const size_t base =
                ((size_t)(jb * 64 + 2 * tkp) * KVUPW + h * 256 + 128) >> 1;
            const uint32_t a = kvu[base + dvp];
            const uint32_t b = kvu[base + (KVUPW >> 1) + dvp];
            sV[(2 * dvp) * VS + tkp] = __byte_perm(a, b, 0x5410);
            sV[(2 * dvp + 1) * VS + tkp] = __byte_perm(a, b, 0x7632);
        }
        __syncthreads();

        // ---- S = Q K^T ----
        float S[8][4];
#pragma unroll
        for (int nt = 0; nt < 8; nt++)
#pragma unroll
            for (int j = 0; j < 4; j++) S[nt][j] = 0.f;

#pragma unroll
        for (int ks = 0; ks < 12; ks++) {
            uint32_t a[4];
            ldsm4(a[0], a[1], a[2], a[3], sQb + qoff + ks * 32);
#pragma unroll
            for (int n2 = 0; n2 < 4; n2++) {
                uint32_t b0, b1, b2, b3;
                ldsm4(b0, b1, b2, b3, sKb + koff + n2 * (16 * KS * 4) + ks * 32);
                mma_f16(S[2 * n2], a, b0, b1);
                mma_f16(S[2 * n2 + 1], a, b2, b3);
            }
        }

        // ---- causal mask ----
        if (jb >= 2 * ib) {
#pragma unroll
            for (int nt = 0; nt < 8; nt++) {
                const int kc = jb * 64 + nt * 8 + c2 * 2;
                if (kc > qr0)     S[nt][0] = -1e30f;
                if (kc + 1 > qr0) S[nt][1] = -1e30f;
                if (kc > qr0 + 8)     S[nt][2] = -1e30f;
                if (kc + 1 > qr0 + 8) S[nt][3] = -1e30f;
            }
        }

        // ---- online softmax (log2 domain, f16x2 exp) ----
        float mx0 = -INFINITY, mx1 = -INFINITY;
#pragma unroll
        for (int nt = 0; nt < 8; nt++) {
            mx0 = fmaxf(mx0, fmaxf(S[nt][0], S[nt][1]));
            mx1 = fmaxf(mx1, fmaxf(S[nt][2], S[nt][3]));
        }
        mx0 = fmaxf(mx0, __shfl_xor_sync(0xffffffffu, mx0, 1));
        mx0 = fmaxf(mx0, __shfl_xor_sync(0xffffffffu, mx0, 2));
        mx1 = fmaxf(mx1, __shfl_xor_sync(0xffffffffu, mx1, 1));
        mx1 = fmaxf(mx1, __shfl_xor_sync(0xffffffffu, mx1, 2));
        const float mn0 = fmaxf(m0, mx0), mn1 = fmaxf(m1, mx1);
        const float al0 = ex2f(m0 - mn0), al1 = ex2f(m1 - mn1);
        m0 = mn0; m1 = mn1;
        const int prow = wid * 16 + r;
#pragma unroll
        for (int nt = 0; nt < 8; nt++) {
            sP[prow * PS + nt * 4 + c2] =
                ex2h2(h2u(__floats2half2_rn(S[nt][0] - mn0, S[nt][1] - mn0)));
            sP[(prow + 8) * PS + nt * 4 + c2] =
                ex2h2(h2u(__floats2half2_rn(S[nt][2] - mn1, S[nt][3] - mn1)));
        }
#pragma unroll
        for (int nt = 0; nt < 16; nt++) {
            O[nt][0] *= al0; O[nt][1] *= al0;
            O[nt][2] *= al1; O[nt][3] *= al1;
        }
        Osum[0] *= al0; Osum[1] *= al0;
        Osum[2] *= al1; Osum[3] *= al1;
        __syncwarp();

        // ---- O += P V (ones column accumulates row sums into Osum) ----
#pragma unroll
        for (int kf = 0; kf < 4; kf++) {
            uint32_t a[4];
            ldsm4(a[0], a[1], a[2], a[3], sPb + poff + kf * 32);
#pragma unroll
            for (int n2 = 0; n2 < 8; n2++) {
                uint32_t b0, b1, b2, b3;
                ldsm4(b0, b1, b2, b3, sVb + voff + n2 * (16 * VS * 4) + kf * 32);
                mma_f16(O[2 * n2], a, b0, b1);
                mma_f16(O[2 * n2 + 1], a, b2, b3);
            }
            uint32_t o0, o1;
            ldsm2(o0, o1, sVb + ooff + kf * 32);
            mma_f16(Osum, a, o0, o1);
        }
    }

    // ---- epilogue: extract row sums, normalize, store fp16 ----
    const float s0 = __shfl_sync(0xffffffffu, Osum[0], lane & ~3);
    const float s1 = __shfl_sync(0xffffffffu, Osum[2], lane & ~3);
    const float inv0 = 1.f / s0, inv1 = 1.f / s1;
    const int row0 = ib * 128 + wid * 16 + r;
    __half2* out2 = (__half2*)out;
#pragma unroll
    for (int nt = 0; nt < 16; nt++) {
        const int col = h * DV + nt * 8 + c2 * 2;
        out2[((size_t)row0 * ATTNW + col) >> 1] =
            __floats2half2_rn(O[nt][0] * inv0, O[nt][1] * inv0);
        out2[((size_t)(row0 + 8) * ATTNW + col) >> 1] =
            __floats2half2_rn(O[nt][2] * inv1, O[nt][3] * inv1);
    }
}

// ---------------- launch -----------------------------------------------------
extern "C" void kernel_launch(void* const* d_in, const int* in_sizes, int n_in,
                              void* d_out, int out_size) {
    const int* positions = (const int*)d_in[0];
    const float* hidden = (const float*)d_in[1];
    const float* w_qa = (const float*)d_in[2];
    const float* gamma_q = (const float*)d_in[3];
    const float* w_qb = (const float*)d_in[4];
    const float* w_kva = (const float*)d_in[5];
    const float* gamma_kv = (const float*)d_in[6];
    const float* w_kvb = (const float*)d_in[7];
    const float* w_o = (const float*)d_in[8];
    float* out = (float*)d_out;

    __half *hid_h, *wcmbT, *wqbT, *wkvbT, *woT, *cmbh, *qh, *kvuph, *kpeh, *attnh;
    cudaGetSymbolAddress((void**)&hid_h, g_hid_h);
    cudaGetSymbolAddress((void**)&wcmbT, g_wcmbT);
    cudaGetSymbolAddress((void**)&wqbT, g_wqbT);
    cudaGetSymbolAddress((void**)&wkvbT, g_wkvbT);
    cudaGetSymbolAddress((void**)&woT, g_woT);
    cudaGetSymbolAddress((void**)&cmbh, g_cmbh);
    cudaGetSymbolAddress((void**)&qh, g_qh);
    cudaGetSymbolAddress((void**)&kvuph, g_kvuph);
    cudaGetSymbolAddress((void**)&kpeh, g_kpeh);
    cudaGetSymbolAddress((void**)&attnh, g_attnh);

    cudaFuncSetAttribute(gemm_h, cudaFuncAttributeMaxDynamicSharedMemorySize, GSMEM);
    cudaFuncSetAttribute(flash_h, cudaFuncAttributeMaxDynamicSharedMemorySize,
                         FLASH_SMEM);

    const float SCALE_L2E = 0.07216878364870323f * 1.4426950408889634f;
    const int MB = T_TOK / 128;  // 16
    const dim3 tb(32, 8);

    // 1: hidden fp32 -> fp16
    cvt_h_kernel<<<2048, 256>>>(hidden, hid_h, T_TOK * HIDDEN / 4);
    // 2,3: transpose-convert [w_qa | w_kva] -> wcmbT [2112][5120]
    cvtT_kernel<<<dim3(QLORA / 32, HIDDEN / 32), tb>>>(w_qa, wcmbT, HIDDEN, QLORA, 0);
    cvtT_kernel<<<dim3(KV_W / 32, HIDDEN / 32), tb>>>(w_kva, wcmbT, HIDDEN, KV_W, QLORA);
    // 4: merged down-proj [q_a | kv_c | pe->kpe]   [2048,2112]
    gemm_h<<<dim3((CMBW + 127) / 128, MB), 128, GSMEM>>>(
        hid_h, HIDDEN, wcmbT, HIDDEN, cmbh, CMBW, CMBW, HIDDEN,
        1.f, 2, QLORA + KVLORA, 0, positions, kpeh);
    // 5: w_qb -> wqbT [6144][1536]
    cvtT_kernel<<<dim3(QW / 32, QLORA / 32), tb>>>(w_qb, wqbT, QLORA, QW, 0);
    // 6,7: rmsnorm in place
    rmsnorm_h<<<T_TOK, 256>>>(cmbh, gamma_q, QLORA, CMBW);
    rmsnorm_h<<<T_TOK, 256>>>(cmbh + QLORA, gamma_kv, KVLORA, CMBW);
    // 8: q = (q_c @ w_qb) * scale*log2e, q-RoPE fused          [2048,6144]
    gemm_h<<<dim3(QW / 128, MB), 128, GSMEM>>>(
        cmbh, CMBW, wqbT, QLORA, qh, QW, QW, QLORA,
        SCALE_L2E, 1, 0, 0, positions, kpeh);
    // 9: w_kvb -> wkvbT [8192][512]
    cvtT_kernel<<<dim3(KVUPW / 32, KVLORA / 32), tb>>>(w_kvb, wkvbT, KVLORA, KVUPW, 0);
    // 10: kv_up = kv_c @ w_kvb                                 [2048,8192]
    gemm_h<<<dim3(KVUPW / 128, MB), 128, GSMEM>>>(
        cmbh + QLORA, CMBW, wkvbT, KVLORA, kvuph, KVUPW, KVUPW, KVLORA,
        1.f, 0, 0, 0, positions, kpeh);
    // 11: w_o -> woT [5120][4096]
    cvtT_kernel<<<dim3(HIDDEN / 32, ATTNW / 32), tb>>>(w_o, woT, ATTNW, HIDDEN, 0);
    // 12: attention
    flash_h<<<dim3(T_TOK / 128, NH), 256, FLASH_SMEM>>>(qh, kvuph, kpeh, attnh);
    // 13: out = attn @ w_o (fp32 out)                          [2048,5120]
    gemm_h<<<dim3(HIDDEN / 128, MB), 128, GSMEM>>>(
        attnh, ATTNW, woT, ATTNW, out, HIDDEN, HIDDEN, ATTNW,
        1.f, 0, 0, 1, positions, kpeh);
}

// round 15
// speedup vs baseline: 1.2633x; 1.2633x over previous
#include <cuda_runtime.h>
#include <cuda_fp16.h>
#include <math.h>
#include <stdint.h>

#define T_TOK 2048
#define HIDDEN 5120
#define NH 32
#define DQ 128
#define DR 64
#define DV 128
#define QLORA 1536
#define KVLORA 512
#define KV_W (KVLORA + DR)        // 576
#define QDIM (DQ + DR)            // 192
#define KVUPW (NH * (DQ + DV))    // 8192
#define QW (NH * QDIM)            // 6144
#define ATTNW (NH * DV)           // 4096
#define CMBW (QLORA + KV_W)       // 2112

// ---------------- scratch (device globals; no runtime allocation) ----------
__device__ __half g_hid_h[T_TOK * HIDDEN];
__device__ __half g_wcmbT[CMBW * HIDDEN];    // [2112][5120] K-major
__device__ __half g_wqbT[QW * QLORA];        // [6144][1536]
__device__ __half g_wkvbT[KVUPW * KVLORA];   // [8192][512]
__device__ __half g_woT[HIDDEN * ATTNW];     // [5120][4096]
__device__ __half g_cmbh[T_TOK * CMBW];
__device__ __half g_qh[T_TOK * QW];
__device__ __half g_kvuph[T_TOK * KVUPW];
__device__ __half g_kpeh[T_TOK * DR];
__device__ __half g_attnh[T_TOK * ATTNW];

// ======================= helpers ===========================================
__device__ __forceinline__ uint32_t smem_u32(const void* p) {
    uint32_t a;
    asm("{ .reg .u64 t; cvta.to.shared.u64 t, %1; cvt.u32.u64 %0, t; }"
        : "=r"(a) : "l"(p));
    return a;
}

__device__ __forceinline__ float ex2f(float x) {
    float y;
    asm("ex2.approx.ftz.f32 %0, %1;" : "=f"(y) : "f"(x));
    return y;
}

__device__ __forceinline__ uint32_t ex2h2(uint32_t x) {
    uint32_t y;
    asm("ex2.approx.f16x2 %0, %1;" : "=r"(y) : "r"(x));
    return y;
}

__device__ __forceinline__ void mma_f16(float c[4], const uint32_t a[4],
                                        uint32_t b0, uint32_t b1) {
    asm volatile(
        "mma.sync.aligned.m16n8k16.row.col.f32.f16.f16.f32 "
        "{%0,%1,%2,%3}, {%4,%5,%6,%7}, {%8,%9}, {%0,%1,%2,%3};"
        : "+f"(c[0]), "+f"(c[1]), "+f"(c[2]), "+f"(c[3])
        : "r"(a[0]), "r"(a[1]), "r"(a[2]), "r"(a[3]), "r"(b0), "r"(b1));
}

__device__ __forceinline__ void ldsm4(uint32_t& r0, uint32_t& r1,
                                      uint32_t& r2, uint32_t& r3, uint32_t addr) {
    asm volatile("ldmatrix.sync.aligned.m8n8.x4.shared.b16 {%0,%1,%2,%3}, [%4];"
                 : "=r"(r0), "=r"(r1), "=r"(r2), "=r"(r3) : "r"(addr));
}

__device__ __forceinline__ void ldsm4t(uint32_t& r0, uint32_t& r1,
                                       uint32_t& r2, uint32_t& r3, uint32_t addr) {
    asm volatile("ldmatrix.sync.aligned.m8n8.x4.trans.shared.b16 {%0,%1,%2,%3}, [%4];"
                 : "=r"(r0), "=r"(r1), "=r"(r2), "=r"(r3) : "r"(addr));
}

__device__ __forceinline__ void ldsm2t(uint32_t& r0, uint32_t& r1, uint32_t addr) {
    asm volatile("ldmatrix.sync.aligned.m8n8.x2.trans.shared.b16 {%0,%1}, [%2];"
                 : "=r"(r0), "=r"(r1) : "r"(addr));
}

__device__ __forceinline__ uint32_t h2u(__half2 h) {
    return *reinterpret_cast<uint32_t*>(&h);
}

// ---------------- fp32 -> fp16 conversion kernels --------------------------
__global__ void cvt_h_kernel(const float* __restrict__ in,
                             __half* __restrict__ o, int n4) {
    __half2* o2 = (__half2*)o;
    for (int i = blockIdx.x * 256 + threadIdx.x; i < n4; i += gridDim.x * 256) {
        float4 v = ((const float4*)in)[i];
        o2[2 * i] = __floats2half2_rn(v.x, v.y);
        o2[2 * i + 1] = __floats2half2_rn(v.z, v.w);
    }
}

// transpose + convert: in [Kd][Nd] fp32 -> out rows [orow + n][Kd] fp16
__global__ void cvtT_kernel(const float* __restrict__ in,
                            __half* __restrict__ out,
                            int Kd, int Nd, int orow) {
    __shared__ float t[32][33];
    const int n0 = blockIdx.x * 32, k0 = blockIdx.y * 32;
    const int x = threadIdx.x, y = threadIdx.y;  // (32,8)
#pragma unroll
    for (int j = 0; j < 4; j++)
        t[y + 8 * j][x] = in[(size_t)(k0 + y + 8 * j) * Nd + n0 + x];
    __syncthreads();
#pragma unroll
    for (int j = 0; j < 4; j++)
        out[(size_t)(orow + n0 + y + 8 * j) * Kd + k0 + x] =
            __float2half_rn(t[x][y + 8 * j]);
}

// ---------------- RoPE frequency -------------------------------------------
#define L2T_32 0.41524101186091903f   // log2(10000)/32
__device__ __forceinline__ float rope_freq(int i) {
    return exp2f(-(float)(i & 31) * L2T_32);
}

// ======================= fp16 mma.sync GEMM (R13 config) ===================
// C[M,N] = A[M,K] @ B[K,N]; A fp16 row-major [M][K]; B pre-transposed fp16
// [N][K]. M mult of 128, K mult of 32. CTA 128x128, BK=32, 3-stage cp.async,
// 256 thr (8 warps 4x2, warp tile 32x64), m16n8k16, ldmatrix.
#define RS 20
#define GSTG (128 * RS * 4)          // 10240 B per operand
#define GSTAGE (2 * GSTG)            // 20480 B per stage
#define GSMEM (3 * GSTAGE)           // 61440 B

__device__ __forceinline__ void g_load(uint32_t sbase, int s,
        const __half* __restrict__ A, int lda,
        const __half* __restrict__ BT, int ldb,
        int brow, int bcol, int N, int k0, int tid) {
    const uint32_t sA = sbase + s * GSTAGE;
    const uint32_t sB = sA + GSTG;
#pragma unroll
    for (int it = 0; it < 2; it++) {
        const int f = it * 256 + tid;
        const int r = f >> 2, c = f & 3;
        const uint32_t dst = sA + (r * RS + c * 4) * 4;
        const __half* src = A + (size_t)(brow + r) * lda + k0 + c * 8;
        asm volatile("cp.async.ca.shared.global [%0], [%1], 16;"
                     :: "r"(dst), "l"(src) : "memory");
    }
#pragma unroll
    for (int it = 0; it < 2; it++) {
        const int f = it * 256 + tid;
        const int r = f >> 2, c = f & 3;
        const uint32_t dst = sB + (r * RS + c * 4) * 4;
        const __half* src = BT + (size_t)(bcol + r) * ldb + k0 + c * 8;
        const int sz = (bcol + r < N) ? 16 : 0;
        asm volatile("cp.async.ca.shared.global [%0], [%1], 16, %2;"
                     :: "r"(dst), "l"(src), "r"(sz) : "memory");
    }
    asm volatile("cp.async.commit_group;" ::: "memory");
}

// mode: 0 plain; 1 q-RoPE ((col%192)>=128 rotated); 2 pe-split (col>=pe0 ->
// kpe). outfp32: C treated as float* (final output), else __half*.
__global__ __launch_bounds__(256, 2) void gemm_h(
        const __half* __restrict__ A, int lda,
        const __half* __restrict__ BT, int ldb,
        void* __restrict__ Cv, int ldc, int N, int K,
        float oscale, int mode, int pe0, int outfp32,
        const int* __restrict__ pos, __half* __restrict__ kpe) {
    extern __shared__ char sm[];
    const uint32_t sbase = smem_u32(sm);
    const int tid = threadIdx.x;
    const int lane = tid & 31;
    const int wid = tid >> 5;
    const int wm = wid >> 1, wn = wid & 1;
    const int brow = blockIdx.y * 128;
    const int bcol = blockIdx.x * 128;
    const int r = lane >> 2, c2 = lane & 3;

    float acc[2][8][4];
#pragma unroll
    for (int mi = 0; mi < 2; mi++)
#pragma unroll
        for (int ni = 0; ni < 8; ni++)
#pragma unroll
            for (int j = 0; j < 4; j++) acc[mi][ni][j] = 0.f;

    const uint32_t aoff = ((wm * 32 + (lane & 7) + 8 * ((lane >> 3) & 1)) * RS
                           + 4 * (lane >> 4)) * 4;
    const uint32_t boff = ((wn * 64 + (lane & 7) + 8 * (lane >> 4)) * RS
                           + 4 * ((lane >> 3) & 1)) * 4;

    const int nch = K / 32;
    g_load(sbase, 0, A, lda, BT, ldb, brow, bcol, N, 0, tid);
    g_load(sbase, 1, A, lda, BT, ldb, brow, bcol, N, 32, tid);

    for (int i = 0; i < nch; i++) {
        const int s = i % 3;
        if (i + 1 < nch) {
            asm volatile("cp.async.wait_group 1;" ::: "memory");
        } else {
            asm volatile("cp.async.wait_group 0;" ::: "memory");
        }
        __syncthreads();

        const uint32_t sAb = sbase + s * GSTAGE;
        const uint32_t sBb = sAb + GSTG;

#pragma unroll
        for (int t = 0; t < 2; t++) {
            uint32_t a[2][4];
            ldsm4(a[0][0], a[0][1], a[0][2], a[0][3], sAb + aoff + t * 32);
            ldsm4(a[1][0], a[1][1], a[1][2], a[1][3],
                  sAb + aoff + 16 * RS * 4 + t * 32);
#pragma unroll
            for (int n2 = 0; n2 < 4; n2++) {
                uint32_t b0, b1, b2, b3;
                ldsm4(b0, b1, b2, b3, sBb + boff + n2 * (16 * RS * 4) + t * 32);
                mma_f16(acc[0][2 * n2], a[0], b0, b1);
                mma_f16(acc[1][2 * n2], a[1], b0, b1);
                mma_f16(acc[0][2 * n2 + 1], a[0], b2, b3);
                mma_f16(acc[1][2 * n2 + 1], a[1], b2, b3);
            }
        }
        if (i + 2 < nch)
            g_load(sbase, (i + 2) % 3, A, lda, BT, ldb, brow, bcol, N,
                   (i + 2) * 32, tid);
    }

    // ---- epilogue ----
    __half* Ch = (__half*)Cv;
    float* Cf = (float*)Cv;
#pragma unroll
    for (int mi = 0; mi < 2; mi++) {
        const int r0 = brow + wm * 32 + mi * 16 + r;
        const int r1 = r0 + 8;
        float fp0 = 0.f, fp1 = 0.f;
        if (mode != 0) { fp0 = (float)pos[r0]; fp1 = (float)pos[r1]; }
#pragma unroll
        for (int ni = 0; ni < 8; ni++) {
            const int col = bcol + wn * 64 + ni * 8 + c2 * 2;
            if (col >= N) continue;
            float x0 = acc[mi][ni][0] * oscale, x1 = acc[mi][ni][1] * oscale;
            float x2 = acc[mi][ni][2] * oscale, x3 = acc[mi][ni][3] * oscale;

            if (mode == 1) {
                const int d = col % QDIM;
                if (d >= DQ) {
                    const int i0 = d - DQ;
                    const float f0 = rope_freq(i0), f1 = rope_freq(i0 + 1);
                    float s0, c0, s1, c1;
                    sincosf(fp0 * f0, &s0, &c0);
                    sincosf(fp0 * f1, &s1, &c1);
                    float nx0 = x0 * c0 - x1 * s0;
                    float nx1 = x1 * c1 + x0 * s1;
                    x0 = nx0; x1 = nx1;
                    sincosf(fp1 * f0, &s0, &c0);
                    sincosf(fp1 * f1, &s1, &c1);
                    float nx2 = x2 * c0 - x3 * s0;
                    float nx3 = x3 * c1 + x2 * s1;
                    x2 = nx2; x3 = nx3;
                }
            } else if (mode == 2 && col >= pe0) {
                const int i0 = col - pe0;
                const float f0 = rope_freq(i0), f1 = rope_freq(i0 + 1);
                float s0, c0, s1, c1;
                sincosf(fp0 * f0, &s0, &c0);
                sincosf(fp0 * f1, &s1, &c1);
                ((__half2*)kpe)[((size_t)r0 * DR + i0) >> 1] =
                    __floats2half2_rn(x0 * c0 - x1 * s0, x1 * c1 + x0 * s1);
                sincosf(fp1 * f0, &s0, &c0);
                sincosf(fp1 * f1, &s1, &c1);
                ((__half2*)kpe)[((size_t)r1 * DR + i0) >> 1] =
                    __floats2half2_rn(x2 * c0 - x3 * s0, x3 * c1 + x2 * s1);
                continue;
            }

            if (outfp32) {
                *(float2*)&Cf[(size_t)r0 * ldc + col] = make_float2(x0, x1);
                *(float2*)&Cf[(size_t)r1 * ldc + col] = make_float2(x2, x3);
            } else {
                ((__half2*)Ch)[((size_t)r0 * ldc + col) >> 1] =
                    __floats2half2_rn(x0, x1);
                ((__half2*)Ch)[((size_t)r1 * ldc + col) >> 1] =
                    __floats2half2_rn(x2, x3);
            }
        }
    }
}

// ---------------- RMSNorm in place on fp16 ----------------------------------
__global__ void rmsnorm_h(__half* __restrict__ x, const float* __restrict__ g,
                          int width, int stride) {
    const int row = blockIdx.x;
    __half2* p = (__half2*)(x + (size_t)row * stride);
    const int tid = threadIdx.x;
    const int w2 = width >> 1;
    float s = 0.f;
    for (int i = tid; i < w2; i += 256) {
        float2 f = __half22float2(p[i]);
        s += f.x * f.x + f.y * f.y;
    }
    __shared__ float red[256];
    red[tid] = s;
    __syncthreads();
    for (int o = 128; o > 0; o >>= 1) {
        if (tid < o) red[tid] += red[tid + o];
        __syncthreads();
    }
    const float inv = rsqrtf(red[0] / (float)width + 1e-6f);
    for (int i = tid; i < w2; i += 256) {
        float2 f = __half22float2(p[i]);
        p[i] = __floats2half2_rn(f.x * inv * g[2 * i], f.y * inv * g[2 * i + 1]);
    }
}

// ================ flash attention: fp16 mma + cp.async double buffering ====
// grid (16, 32): 128 q rows/CTA (ib reversed), 8 warps, k-tiles of 64.
// K [tok][192] and V [tok][144] (dv 0..127 data, col 128 = ones for row-sum,
// 129..143 zero) double-buffered via cp.async; V fragments via ldmatrix.trans.
#define QS 100   // sQ [128][96 u32]
#define KS 100   // sK stage [64][96 u32]
#define VS2 72   // sV stage [64][72 u32] = 144 halves
#define PS 36    // sP [128][32 u32]
#define FLASH_SMEM ((128 * QS + 2 * 64 * KS + 2 * 64 * VS2 + 128 * PS) * 4) // 157696

__global__ __launch_bounds__(256, 1) void flash_h(
        const __half* __restrict__ q, const __half* __restrict__ kvup,
        const __half* __restrict__ kpe, __half* __restrict__ out) {
    const int ib = gridDim.x - 1 - blockIdx.x;   // heavy CTAs first
    const int h = blockIdx.y;
    const int tid = threadIdx.x;
    const int lane = tid & 31;
    const int wid = tid >> 5;
    const int r = lane >> 2, c2 = lane & 3;

    extern __shared__ uint32_t fs[];
    uint32_t* sQ = fs;                      // 12800 u32
    uint32_t* sV = sQ + 128 * QS;           // 2 stages x 4608
    uint32_t* sP = sV + 2 * 64 * VS2;       // 4608
    const uint32_t sQb = smem_u32(sQ);
    const uint32_t sKb = sQb + (128 * QS + 2 * 64 * VS2 + 128 * PS) * 4;
    const uint32_t sVb = smem_u32(sV);
    const uint32_t sPb = smem_u32(sP);

    // ---- prefetch helper: issue K+V tile jb into stage s ----
    auto issue_tile = [&](int jb, int s) {
        const int kt0 = jb * 64;
        const uint32_t kb = sKb + s * (64 * KS * 4);
#pragma unroll
        for (int it = 0; it < 6; it++) {
            const int idx = it * 256 + tid;
            const int rr = idx / 24, c = idx % 24;
            const int kt = kt0 + rr;
            const uint32_t dst = kb + (rr * KS + c * 4) * 4;
            const __half* src = (c < 16)
                ? kvup + (size_t)kt * KVUPW + h * 256 + c * 8
                : kpe + (size_t)kt * DR + (c - 16) * 8;
            asm volatile("cp.async.ca.shared.global [%0], [%1], 16;"
                         :: "r"(dst), "l"(src) : "memory");
        }
        const uint32_t vb = sVb + s * (64 * VS2 * 4);
#pragma unroll
        for (int it = 0; it < 4; it++) {
            const int idx = it * 256 + tid;
            const int rr = idx >> 4, c = idx & 15;
            const uint32_t dst = vb + (rr * VS2 + c * 4) * 4;
            const __half* src = kvup + (size_t)(kt0 + rr) * KVUPW + h * 256 + 128 + c * 8;
            asm volatile("cp.async.ca.shared.global [%0], [%1], 16;"
                         :: "r"(dst), "l"(src) : "memory");
        }
        asm volatile("cp.async.commit_group;" ::: "memory");
    };

    issue_tile(0, 0);  // overlap with Q load below

    // Q tile: 128 rows x 192 halves
    for (int idx = tid; idx < 128 * 24; idx += 256) {
        const int rr = idx / 24, d4 = idx % 24;
        *(float4*)&sQ[rr * QS + d4 * 4] =
            *(const float4*)(q + (size_t)(ib * 128 + rr) * QW + h * QDIM + d4 * 8);
    }
    // ones columns of both V stages: u32 cols 64..71 (halves 128..143)
    for (int idx = tid; idx < 2 * 64 * 8; idx += 256) {
        const int st = idx >> 9, rr = (idx >> 3) & 63, c = idx & 7;
        sV[st * 64 * VS2 + rr * VS2 + 64 + c] = (c == 0) ? 0x00003C00u : 0u;
    }

    // ldmatrix per-lane byte offsets
    const uint32_t qoff = ((wid * 16 + (lane & 7) + 8 * ((lane >> 3) & 1)) * QS
                          + 4 * (lane >> 4)) * 4;
    const uint32_t koff = (((lane & 7) + 8 * (lane >> 4)) * KS
                          + 4 * ((lane >> 3) & 1)) * 4;
    const uint32_t poff = ((wid * 16 + (lane & 7) + 8 * ((lane >> 3) & 1)) * PS
                          + 4 * (lane >> 4)) * 4;
    // V trans frags: rows = tok (k), col halves = dv (n)
    const uint32_t voff = (((lane & 7) + 8 * ((lane >> 3) & 1)) * VS2) * 4
                          + (lane >> 4) * 16;
    const uint32_t ooff = (((lane & 7) + 8 * ((lane >> 3) & 1)) * VS2) * 4 + 256;

    const int qr0 = ib * 128 + wid * 16 + r;
    float m0 = -INFINITY, m1 = -INFINITY;
    float O[16][4], Osum[4];
#pragma unroll
    for (int nt = 0; nt < 16; nt++)
#pragma unroll
        for (int j = 0; j < 4; j++) O[nt][j] = 0.f;
#pragma unroll
    for (int j = 0; j < 4; j++) Osum[j] = 0.f;

    const int njb = 2 * ib + 2;
    for (int jb = 0; jb < njb; jb++) {
        const int s = jb & 1;
        __syncthreads();   // prev compute done with stage s^1 (iter0: Q/ones stores ordered)
        if (jb + 1 < njb) {
            issue_tile(jb + 1, s ^ 1);
            asm volatile("cp.async.wait_group 1;" ::: "memory");
        } else {
            asm volatile("cp.async.wait_group 0;" ::: "memory");
        }
        __syncthreads();   // stage s visible to all warps

        const uint32_t sKs = sKb + s * (64 * KS * 4);
        const uint32_t sVs = sVb + s * (64 * VS2 * 4);

        // ---- S = Q K^T ----
        float S[8][4];
#pragma unroll
        for (int nt = 0; nt < 8; nt++)
#pragma unroll
            for (int j = 0; j < 4; j++) S[nt][j] = 0.f;

#pragma unroll
        for (int ks = 0; ks < 12; ks++) {
            uint32_t a[4];
            ldsm4(a[0], a[1], a[2], a[3], sQb + qoff + ks * 32);
#pragma unroll
            for (int n2 = 0; n2 < 4; n2++) {
                uint32_t b0, b1, b2, b3;
                ldsm4(b0, b1, b2, b3, sKs + koff + n2 * (16 * KS * 4) + ks * 32);
                mma_f16(S[2 * n2], a, b0, b1);
                mma_f16(S[2 * n2 + 1], a, b2, b3);
            }
        }

        // ---- causal mask ----
        if (jb >= 2 * ib) {
#pragma unroll
            for (int nt = 0; nt < 8; nt++) {
                const int kc = jb * 64 + nt * 8 + c2 * 2;
                if (kc > qr0)     S[nt][0] = -1e30f;
                if (kc + 1 > qr0) S[nt][1] = -1e30f;
                if (kc > qr0 + 8)     S[nt][2] = -1e30f;
                if (kc + 1 > qr0 + 8) S[nt][3] = -1e30f;
            }
        }

        // ---- online softmax (log2 domain, f16x2 exp) ----
        float mx0 = -INFINITY, mx1 = -INFINITY;
#pragma unroll
        for (int nt = 0; nt < 8; nt++) {
            mx0 = fmaxf(mx0, fmaxf(S[nt][0], S[nt][1]));
            mx1 = fmaxf(mx1, fmaxf(S[nt][2], S[nt][3]));
        }
        mx0 = fmaxf(mx0, __shfl_xor_sync(0xffffffffu, mx0, 1));
        mx0 = fmaxf(mx0, __shfl_xor_sync(0xffffffffu, mx0, 2));
        mx1 = fmaxf(mx1, __shfl_xor_sync(0xffffffffu, mx1, 1));
        mx1 = fmaxf(mx1, __shfl_xor_sync(0xffffffffu, mx1, 2));
        const float mn0 = fmaxf(m0, mx0), mn1 = fmaxf(m1, mx1);
        const float al0 = ex2f(m0 - mn0), al1 = ex2f(m1 - mn1);
        m0 = mn0; m1 = mn1;
        const int prow = wid * 16 + r;
#pragma unroll
        for (int nt = 0; nt < 8; nt++) {
            sP[prow * PS + nt * 4 + c2] =
                ex2h2(h2u(__floats2half2_rn(S[nt][0] - mn0, S[nt][1] - mn0)));
            sP[(prow + 8) * PS + nt * 4 + c2] =
                ex2h2(h2u(__floats2half2_rn(S[nt][2] - mn1, S[nt][3] - mn1)));
        }
#pragma unroll
        for (int nt = 0; nt < 16; nt++) {
            O[nt][0] *= al0; O[nt][1] *= al0;
            O[nt][2] *= al1; O[nt][3] *= al1;
        }
        Osum[0] *= al0; Osum[1] *= al0;
        Osum[2] *= al1; Osum[3] *= al1;
        __syncwarp();

        // ---- O += P V (ldmatrix.trans on natural-layout V) ----
#pragma unroll
        for (int kf = 0; kf < 4; kf++) {
            uint32_t a[4];
            ldsm4(a[0], a[1], a[2], a[3], sPb + poff + kf * 32);
            const uint32_t vk = sVs + voff + kf * (16 * VS2 * 4);
#pragma unroll
            for (int n2 = 0; n2 < 8; n2++) {
                uint32_t b0, b1, b2, b3;
                ldsm4t(b0, b1, b2, b3, vk + n2 * 32);
                mma_f16(O[2 * n2], a, b0, b1);
                mma_f16(O[2 * n2 + 1], a, b2, b3);
            }
            uint32_t o0, o1;
            ldsm2t(o0, o1, sVs + ooff + kf * (16 * VS2 * 4));
            mma_f16(Osum, a, o0, o1);
        }
    }

    // ---- epilogue: extract row sums, normalize, store fp16 ----
    const float s0 = __shfl_sync(0xffffffffu, Osum[0], lane & ~3);
    const float s1 = __shfl_sync(0xffffffffu, Osum[2], lane & ~3);
    const float inv0 = 1.f / s0, inv1 = 1.f / s1;
    const int row0 = ib * 128 + wid * 16 + r;
    __half2* out2 = (__half2*)out;
#pragma unroll
    for (int nt = 0; nt < 16; nt++) {
        const int col = h * DV + nt * 8 + c2 * 2;
        out2[((size_t)row0 * ATTNW + col) >> 1] =
            __floats2half2_rn(O[nt][0] * inv0, O[nt][1] * inv0);
        out2[((size_t)(row0 + 8) * ATTNW + col) >> 1] =
            __floats2half2_rn(O[nt][2] * inv1, O[nt][3] * inv1);
    }
}

// ---------------- launch -----------------------------------------------------
extern "C" void kernel_launch(void* const* d_in, const int* in_sizes, int n_in,
                              void* d_out, int out_size) {
    const int* positions = (const int*)d_in[0];
    const float* hidden = (const float*)d_in[1];
    const float* w_qa = (const float*)d_in[2];
    const float* gamma_q = (const float*)d_in[3];
    const float* w_qb = (const float*)d_in[4];
    const float* w_kva = (const float*)d_in[5];
    const float* gamma_kv = (const float*)d_in[6];
    const float* w_kvb = (const float*)d_in[7];
    const float* w_o = (const float*)d_in[8];
    float* out = (float*)d_out;

    __half *hid_h, *wcmbT, *wqbT, *wkvbT, *woT, *cmbh, *qh, *kvuph, *kpeh, *attnh;
    cudaGetSymbolAddress((void**)&hid_h, g_hid_h);
    cudaGetSymbolAddress((void**)&wcmbT, g_wcmbT);
    cudaGetSymbolAddress((void**)&wqbT, g_wqbT);
    cudaGetSymbolAddress((void**)&wkvbT, g_wkvbT);
    cudaGetSymbolAddress((void**)&woT, g_woT);
    cudaGetSymbolAddress((void**)&cmbh, g_cmbh);
    cudaGetSymbolAddress((void**)&qh, g_qh);
    cudaGetSymbolAddress((void**)&kvuph, g_kvuph);
    cudaGetSymbolAddress((void**)&kpeh, g_kpeh);
    cudaGetSymbolAddress((void**)&attnh, g_attnh);

    cudaFuncSetAttribute(gemm_h, cudaFuncAttributeMaxDynamicSharedMemorySize, GSMEM);
    cudaFuncSetAttribute(flash_h, cudaFuncAttributeMaxDynamicSharedMemorySize,
                         FLASH_SMEM);

    const float SCALE_L2E = 0.07216878364870323f * 1.4426950408889634f;
    const int MB = T_TOK / 128;  // 16
    const dim3 tb(32, 8);

    // 1: hidden fp32 -> fp16
    cvt_h_kernel<<<2048, 256>>>(hidden, hid_h, T_TOK * HIDDEN / 4);
    // 2,3: transpose-convert [w_qa | w_kva] -> wcmbT [2112][5120]
    cvtT_kernel<<<dim3(QLORA / 32, HIDDEN / 32), tb>>>(w_qa, wcmbT, HIDDEN, QLORA, 0);
    cvtT_kernel<<<dim3(KV_W / 32, HIDDEN / 32), tb>>>(w_kva, wcmbT, HIDDEN, KV_W, QLORA);
    // 4: merged down-proj [q_a | kv_c | pe->kpe]   [2048,2112]
    gemm_h<<<dim3((CMBW + 127) / 128, MB), 256, GSMEM>>>(
        hid_h, HIDDEN, wcmbT, HIDDEN, cmbh, CMBW, CMBW, HIDDEN,
        1.f, 2, QLORA + KVLORA, 0, positions, kpeh);
    // 5: w_qb -> wqbT [6144][1536]
    cvtT_kernel<<<dim3(QW / 32, QLORA / 32), tb>>>(w_qb, wqbT, QLORA, QW, 0);
    // 6,7: rmsnorm in place
    rmsnorm_h<<<T_TOK, 256>>>(cmbh, gamma_q, QLORA, CMBW);
    rmsnorm_h<<<T_TOK, 256>>>(cmbh + QLORA, gamma_kv, KVLORA, CMBW);
    // 8: q = (q_c @ w_qb) * scale*log2e, q-RoPE fused          [2048,6144]
    gemm_h<<<dim3(QW / 128, MB), 256, GSMEM>>>(
        cmbh, CMBW, wqbT, QLORA, qh, QW, QW, QLORA,
        SCALE_L2E, 1, 0, 0, positions, kpeh);
    // 9: w_kvb -> wkvbT [8192][512]
    cvtT_kernel<<<dim3(KVUPW / 32, KVLORA / 32), tb>>>(w_kvb, wkvbT, KVLORA, KVUPW, 0);
    // 10: kv_up = kv_c @ w_kvb                                 [2048,8192]
    gemm_h<<<dim3(KVUPW / 128, MB), 256, GSMEM>>>(
        cmbh + QLORA, CMBW, wkvbT, KVLORA, kvuph, KVUPW, KVUPW, KVLORA,
        1.f, 0, 0, 0, positions, kpeh);
    // 11: w_o -> woT [5120][4096]
    cvtT_kernel<<<dim3(HIDDEN / 32, ATTNW / 32), tb>>>(w_o, woT, ATTNW, HIDDEN, 0);
    // 12: attention (double-buffered cp.async pipeline)
    flash_h<<<dim3(T_TOK / 128, NH), 256, FLASH_SMEM>>>(qh, kvuph, kpeh, attnh);
    // 13: out = attn @ w_o (fp32 out)                          [2048,5120]
    gemm_h<<<dim3(HIDDEN / 128, MB), 256, GSMEM>>>(
        attnh, ATTNW, woT, ATTNW, out, HIDDEN, HIDDEN, ATTNW,
        1.f, 0, 0, 1, positions, kpeh);
}